// round 14
// baseline (speedup 1.0000x reference)
#include <cuda_runtime.h>
#include <cuda_bf16.h>
#include <cstdint>
#include <math.h>

#define BATCH 64
#define TLEN  512
#define RNNH  256
#define ENCD  512
#define ZK    640
#define GATES 1024
#define LABEL 128
#define MROWS (BATCH*TLEN)          /* 32768 */
#define OUTN  (4194304)             /* MROWS*LABEL */

typedef __nv_bfloat16 bf16;

// ---------------- scratch (device globals; no allocation allowed) ----------------
__device__ __align__(16) bf16  g_zinb[(size_t)MROWS*ZK];    // [B*T,640] pe|pool (bf16)
__device__ __align__(16) bf16  g_G1b[(size_t)MROWS*GATES];  // z@w_ih^T + b_ih + b_hh (bf16)
__device__ __align__(16) bf16  g_Hwb[(size_t)MROWS*RNNH];   // per-word carry h_j (bf16)
__device__ __align__(16) float g_Cw [(size_t)MROWS*RNNH];   // per-word carry c_j (fp32)
__device__ __align__(16) bf16  g_H2b[(size_t)MROWS*GATES];  // Hw@w_hh^T (bf16)
__device__ __align__(16) bf16  g_hsb[(size_t)MROWS*RNNH];   // per-step LSTM output (bf16)
__device__ __align__(16) bf16  g_encb[(size_t)MROWS*ENCD];  // encoder_out bf16
__device__ __align__(16) bf16  g_cwb [RNNH*ZK];
__device__ __align__(16) bf16  g_wihb[GATES*RNNH];
__device__ __align__(16) bf16  g_whh_bf[GATES*RNNH];
__device__ __align__(16) bf16  g_lwb [LABEL*768];
__device__ int   g_svec[MROWS];
__device__ int   g_cidx[MROWS];
__device__ int   g_bpos[MROWS];
__device__ int   g_wcnt[BATCH];

// fast activations: tanh.approx-based (err ~2^-10, << bf16 gate noise)
__device__ __forceinline__ float tanh_fast(float x){
    float y; asm("tanh.approx.f32 %0, %1;" : "=f"(y) : "f"(x));
    return y;
}
__device__ __forceinline__ float sigf(float x){
    return fmaf(0.5f, tanh_fast(0.5f*x), 0.5f);
}

// ---------------- L0: all f32->bf16 conversions + ballot boundary scan -----------
#define N_ENC4 (MROWS*ENCD/4)
#define N_CW4  (RNNH*ZK/4)
#define N_W4   (GATES*RNNH/4)
#define N_LW4  (LABEL*768/4)
#define N_ALL4 (N_ENC4 + N_CW4 + N_W4 + N_W4 + N_LW4)
#define CONV_BLOCKS ((N_ALL4 + 255)/256)

__device__ __forceinline__ void cvt4(const float* s, bf16* d, long i){
    float4 v = *(const float4*)(s + i*4);
    __nv_bfloat162* o = (__nv_bfloat162*)(d + i*4);
    o[0] = __floats2bfloat162_rn(v.x, v.y);
    o[1] = __floats2bfloat162_rn(v.z, v.w);
}
__global__ void k_conv_scan(const float* __restrict__ enc, const float* __restrict__ cw,
                            const float* __restrict__ wih, const float* __restrict__ whh,
                            const float* __restrict__ lw, const int* __restrict__ bnd){
    if (blockIdx.x < CONV_BLOCKS){
        long i = (long)blockIdx.x*256 + threadIdx.x;
        if (i < N_ENC4){ cvt4(enc, g_encb, i); return; }
        i -= N_ENC4;
        if (i < N_CW4){ cvt4(cw, g_cwb, i); return; }
        i -= N_CW4;
        if (i < N_W4){ cvt4(wih, g_wihb, i); return; }
        i -= N_W4;
        if (i < N_W4){ cvt4(whh, g_whh_bf, i); return; }
        i -= N_W4;
        if (i < N_LW4){ cvt4(lw, g_lwb, i); }
    } else {
        int warp = (blockIdx.x - CONV_BLOCKS)*8 + (threadIdx.x >> 5);  // 0..63
        int lane = threadIdx.x & 31;
        if (warp >= BATCH) return;
        int base = warp*TLEN;
        int cnt = 0, last = 0;
        for (int c = 0; c < TLEN/32; c++){
            int t = c*32 + lane;
            int bv = bnd[base + t];
            unsigned m = __ballot_sync(0xffffffffu, bv == 1);
            unsigned mlt = m & ((1u << lane) - 1u);
            int sv = mlt ? (c*32 + 31 - __clz(mlt)) : last;
            g_svec[base + t] = sv;
            g_cidx[base + t] = cnt + __popc(mlt) - 1;
            if (bv == 1) g_bpos[base + cnt + __popc(mlt)] = t;
            cnt += __popc(m);
            last = m ? (c*32 + 31 - __clz(m)) : last;
        }
        if (lane == 0) g_wcnt[warp] = cnt;
    }
}

// ---------------- L1: build zin = [pos_emb(128) | running word mean(512)] --------
__global__ void __launch_bounds__(512) k_build_zin(
        const float* __restrict__ enc, const int* __restrict__ bnd,
        const int* __restrict__ pos, const float* __restrict__ ptab){
    int b = blockIdx.y;
    int tid = threadIdx.x;
    if (blockIdx.x == 0){
        int dim = tid & 127, tq = tid >> 7;
        for (int t = tq; t < TLEN; t += 4){
            int s = g_svec[b*TLEN + t];
            int p = pos[b*TLEN + s];
            g_zinb[(size_t)(b*TLEN + t)*ZK + dim] = __float2bfloat16(ptab[p*128 + dim]);
        }
    } else {
        int dim = tid;  // 0..511
        float acc = 0.f;
        for (int t = 0; t < TLEN; t += 4){
            float e[4]; int s[4], bb[4];
            #pragma unroll
            for (int j = 0; j < 4; j++){
                e[j]  = enc[(size_t)(b*TLEN + t + j)*ENCD + dim];
                s[j]  = g_svec[b*TLEN + t + j];
                bb[j] = bnd[b*TLEN + t + j];
            }
            #pragma unroll
            for (int j = 0; j < 4; j++){
                int wl = (t + j) - s[j]; if (wl < 1) wl = 1;
                g_zinb[(size_t)(b*TLEN + t + j)*ZK + 128 + dim] =
                    __float2bfloat16(acc / (float)wl);
                acc = (bb[j] == 1) ? e[j] : (acc + e[j]);
            }
        }
    }
}

// ================= mma primitives =================================================
#define SSTR 40  /* smem row stride in bf16 elems (80B, conflict-free for ldmatrix) */

__device__ __forceinline__ void ldm_x4(unsigned addr, unsigned& r0, unsigned& r1,
                                       unsigned& r2, unsigned& r3){
    asm volatile("ldmatrix.sync.aligned.m8n8.x4.shared.b16 {%0,%1,%2,%3}, [%4];"
                 : "=r"(r0), "=r"(r1), "=r"(r2), "=r"(r3) : "r"(addr));
}
__device__ __forceinline__ void mma16816(float* c, const unsigned* a, const unsigned* b){
    asm volatile("mma.sync.aligned.m16n8k16.row.col.f32.bf16.bf16.f32 "
                 "{%0,%1,%2,%3}, {%4,%5,%6,%7}, {%8,%9}, {%0,%1,%2,%3};"
                 : "+f"(c[0]), "+f"(c[1]), "+f"(c[2]), "+f"(c[3])
                 : "r"(a[0]), "r"(a[1]), "r"(a[2]), "r"(a[3]), "r"(b[0]), "r"(b[1]));
}

// ---------------- L2: fused z + G1 GEMM ------------------------------------------
#define ZS_OFF   0
#define ZS_TILE  (128*SSTR*2)          /* 10240 B per k-tile */
#define ZG_SA    (8*ZS_TILE)           /* 81920 */
#define ZG_SW    (ZG_SA + 128*SSTR*2)  /* 92160 */
#define ZG_SMEM  (ZG_SW + 128*SSTR*2)  /* 102400 */
extern __shared__ char chsm[];

__global__ void __launch_bounds__(256) k_zg1(const float* __restrict__ cb,
                                             const float* __restrict__ bih,
                                             const float* __restrict__ bhh){
    bf16* zS = (bf16*)(chsm + ZS_OFF);
    bf16* sA = (bf16*)(chsm + ZG_SA);
    bf16* sW = (bf16*)(chsm + ZG_SW);
    int row0 = blockIdx.x * 128;
    int tid = threadIdx.x;
    int lane = tid & 31, wid = tid >> 5;
    int warp_m = wid & 3, warp_n = wid >> 2;
    int lrow = tid >> 2, lseg = tid & 3;

    unsigned sAb = (unsigned)__cvta_generic_to_shared(sA);
    unsigned sWb = (unsigned)__cvta_generic_to_shared(sW);
    unsigned zSb = (unsigned)__cvta_generic_to_shared(zS);
    unsigned aOff = (unsigned)(((warp_m*32 + (lane&15))*SSTR + (lane>>4)*8)*2);
    unsigned bOff = (unsigned)(((warp_n*64 + ((lane>>4)<<3) + (lane&7))*SSTR
                               + ((lane>>3)&1)*8)*2);

    for (int ch = 0; ch < 2; ch++){
        int col0 = ch*128;
        const bf16* Ap = g_zinb + (size_t)(row0 + lrow)*ZK + lseg*8;
        const bf16* Wp = g_cwb  + (size_t)(col0 + lrow)*ZK + lseg*8;
        float acc[2][8][4];
        #pragma unroll
        for (int mi=0;mi<2;mi++)
            #pragma unroll
            for (int j=0;j<8;j++)
                #pragma unroll
                for (int q=0;q<4;q++) acc[mi][j][q] = 0.f;
        uint4 a0 = *(const uint4*)(Ap);
        uint4 a1 = *(const uint4*)(Ap + (size_t)64*ZK);
        uint4 w0 = *(const uint4*)(Wp);
        uint4 w1 = *(const uint4*)(Wp + (size_t)64*ZK);
        for (int k0 = 0; k0 < ZK; k0 += 32){
            *(uint4*)&sA[lrow*SSTR + lseg*8]       = a0;
            *(uint4*)&sA[(lrow+64)*SSTR + lseg*8]  = a1;
            *(uint4*)&sW[lrow*SSTR + lseg*8]       = w0;
            *(uint4*)&sW[(lrow+64)*SSTR + lseg*8]  = w1;
            __syncthreads();
            if (k0 + 32 < ZK){
                a0 = *(const uint4*)(Ap + k0 + 32);
                a1 = *(const uint4*)(Ap + (size_t)64*ZK + k0 + 32);
                w0 = *(const uint4*)(Wp + k0 + 32);
                w1 = *(const uint4*)(Wp + (size_t)64*ZK + k0 + 32);
            }
            #pragma unroll
            for (int ks = 0; ks < 32; ks += 16){
                unsigned af[2][4], bfg[4][4];
                #pragma unroll
                for (int mi=0;mi<2;mi++)
                    ldm_x4(sAb + aOff + mi*16*SSTR*2 + ks*2,
                           af[mi][0],af[mi][1],af[mi][2],af[mi][3]);
                #pragma unroll
                for (int p=0;p<4;p++)
                    ldm_x4(sWb + bOff + p*16*SSTR*2 + ks*2,
                           bfg[p][0],bfg[p][1],bfg[p][2],bfg[p][3]);
                #pragma unroll
                for (int mi=0;mi<2;mi++)
                    #pragma unroll
                    for (int j=0;j<8;j++)
                        mma16816(acc[mi][j], af[mi], &bfg[j>>1][(j&1)*2]);
            }
            __syncthreads();
        }
        #pragma unroll
        for (int mi=0;mi<2;mi++){
            #pragma unroll
            for (int j=0;j<8;j++){
                #pragma unroll
                for (int q=0;q<2;q++){
                    int ml = warp_m*32 + mi*16 + q*8 + (lane>>2);
                    int n  = col0 + warp_n*64 + j*8 + (lane&3)*2;
                    float v0 = tanh_fast(acc[mi][j][q*2+0] + cb[n]);
                    float v1 = tanh_fast(acc[mi][j][q*2+1] + cb[n+1]);
                    if (((row0 + ml) & 511) == 0){ v0 = 0.f; v1 = 0.f; }
                    int kt = n >> 5, kk = n & 31;
                    *(__nv_bfloat162*)&zS[kt*128*SSTR + ml*SSTR + kk] =
                        __floats2bfloat162_rn(v0, v1);
                }
            }
        }
        __syncthreads();
    }

    for (int nt = 0; nt < 8; nt++){
        int col0 = nt*128;
        const bf16* Wp = g_wihb + (size_t)(col0 + lrow)*RNNH + lseg*8;
        float acc[2][8][4];
        #pragma unroll
        for (int mi=0;mi<2;mi++)
            #pragma unroll
            for (int j=0;j<8;j++)
                #pragma unroll
                for (int q=0;q<4;q++) acc[mi][j][q] = 0.f;
        uint4 w0 = *(const uint4*)(Wp);
        uint4 w1 = *(const uint4*)(Wp + (size_t)64*RNNH);
        for (int kt = 0; kt < 8; kt++){
            *(uint4*)&sW[lrow*SSTR + lseg*8]       = w0;
            *(uint4*)&sW[(lrow+64)*SSTR + lseg*8]  = w1;
            __syncthreads();
            if (kt < 7){
                w0 = *(const uint4*)(Wp + (kt+1)*32);
                w1 = *(const uint4*)(Wp + (size_t)64*RNNH + (kt+1)*32);
            }
            unsigned zBase = zSb + kt*ZS_TILE;
            #pragma unroll
            for (int ks = 0; ks < 32; ks += 16){
                unsigned af[2][4], bfg[4][4];
                #pragma unroll
                for (int mi=0;mi<2;mi++)
                    ldm_x4(zBase + aOff + mi*16*SSTR*2 + ks*2,
                           af[mi][0],af[mi][1],af[mi][2],af[mi][3]);
                #pragma unroll
                for (int p=0;p<4;p++)
                    ldm_x4(sWb + bOff + p*16*SSTR*2 + ks*2,
                           bfg[p][0],bfg[p][1],bfg[p][2],bfg[p][3]);
                #pragma unroll
                for (int mi=0;mi<2;mi++)
                    #pragma unroll
                    for (int j=0;j<8;j++)
                        mma16816(acc[mi][j], af[mi], &bfg[j>>1][(j&1)*2]);
            }
            __syncthreads();
        }
        #pragma unroll
        for (int mi=0;mi<2;mi++){
            #pragma unroll
            for (int j=0;j<8;j++){
                #pragma unroll
                for (int q=0;q<2;q++){
                    int m = row0 + warp_m*32 + mi*16 + q*8 + (lane>>2);
                    int n = col0 + warp_n*64 + j*8 + (lane&3)*2;
                    float v0 = acc[mi][j][q*2+0] + bih[n]   + bhh[n];
                    float v1 = acc[mi][j][q*2+1] + bih[n+1] + bhh[n+1];
                    *(__nv_bfloat162*)&g_G1b[(size_t)m*GATES + n] =
                        __floats2bfloat162_rn(v0, v1);
                }
            }
        }
    }
}

// ---------------- generic bf16 mma GEMM (used for H2, EPI 2 only) -----------------
template<int EPI>
__global__ void __launch_bounds__(256) k_gemm_mma(
        const bf16* __restrict__ A, const bf16* __restrict__ W,
        bf16* __restrict__ Cb, int K, int N,
        const float* __restrict__ bias1, const float* __restrict__ bias2){
    int row0 = blockIdx.y * 128;
    int col0 = blockIdx.x * 128;
    if (EPI == 2){
        int b = row0 >> 9;
        if ((row0 & 511) >= g_wcnt[b]) return;
    }
    __shared__ bf16 sA[128*SSTR];
    __shared__ bf16 sW[128*SSTR];
    int tid = threadIdx.x;
    int lane = tid & 31, wid = tid >> 5;
    int warp_m = wid & 3, warp_n = wid >> 2;
    int lrow = tid >> 2, lseg = tid & 3;

    const bf16* Ap = A + (size_t)(row0 + lrow)*K + lseg*8;
    const bf16* Wp = W + (size_t)(col0 + lrow)*K + lseg*8;

    unsigned sAb = (unsigned)__cvta_generic_to_shared(sA);
    unsigned sWb = (unsigned)__cvta_generic_to_shared(sW);
    unsigned aAddr = sAb + (unsigned)(((warp_m*32 + (lane&15))*SSTR + (lane>>4)*8)*2);
    unsigned bAddr = sWb + (unsigned)(((warp_n*64 + ((lane>>4)<<3) + (lane&7))*SSTR
                                      + ((lane>>3)&1)*8)*2);
    float acc[2][8][4];
    #pragma unroll
    for (int mi=0;mi<2;mi++)
        #pragma unroll
        for (int j=0;j<8;j++)
            #pragma unroll
            for (int q=0;q<4;q++) acc[mi][j][q] = 0.f;

    uint4 a0 = *(const uint4*)(Ap);
    uint4 a1 = *(const uint4*)(Ap + (size_t)64*K);
    uint4 w0 = *(const uint4*)(Wp);
    uint4 w1 = *(const uint4*)(Wp + (size_t)64*K);

    for (int k0 = 0; k0 < K; k0 += 32){
        *(uint4*)&sA[lrow*SSTR + lseg*8]       = a0;
        *(uint4*)&sA[(lrow+64)*SSTR + lseg*8]  = a1;
        *(uint4*)&sW[lrow*SSTR + lseg*8]       = w0;
        *(uint4*)&sW[(lrow+64)*SSTR + lseg*8]  = w1;
        __syncthreads();
        if (k0 + 32 < K){
            a0 = *(const uint4*)(Ap + k0 + 32);
            a1 = *(const uint4*)(Ap + (size_t)64*K + k0 + 32);
            w0 = *(const uint4*)(Wp + k0 + 32);
            w1 = *(const uint4*)(Wp + (size_t)64*K + k0 + 32);
        }
        #pragma unroll
        for (int ks = 0; ks < 32; ks += 16){
            unsigned af[2][4], bfg[4][4];
            #pragma unroll
            for (int mi=0;mi<2;mi++)
                ldm_x4(aAddr + mi*16*SSTR*2 + ks*2, af[mi][0],af[mi][1],af[mi][2],af[mi][3]);
            #pragma unroll
            for (int p=0;p<4;p++)
                ldm_x4(bAddr + p*16*SSTR*2 + ks*2, bfg[p][0],bfg[p][1],bfg[p][2],bfg[p][3]);
            #pragma unroll
            for (int mi=0;mi<2;mi++)
                #pragma unroll
                for (int j=0;j<8;j++)
                    mma16816(acc[mi][j], af[mi], &bfg[j>>1][(j&1)*2]);
        }
        __syncthreads();
    }
    #pragma unroll
    for (int mi=0;mi<2;mi++){
        #pragma unroll
        for (int j=0;j<8;j++){
            #pragma unroll
            for (int q=0;q<2;q++){
                int m = row0 + warp_m*32 + mi*16 + q*8 + (lane>>2);
                int n = col0 + warp_n*64 + j*8 + (lane&3)*2;
                *(__nv_bfloat162*)&Cb[(size_t)m*N + n] =
                    __floats2bfloat162_rn(acc[mi][j][q*2+0], acc[mi][j][q*2+1]);
            }
        }
    }
}

// ---------------- L3: cluster-4 chain, in-warp gate gather, st.async exchange ----
// 32 clusters x 4 CTAs, 2 batches each, 256 threads. Lane mapping: warp w, lane λ:
// element e = w*8 + (λ>>2), gate q = λ&3, global row G = q*256 + 64r + e. Each
// thread matvecs its row for BOTH batches (weights read once). Gates gathered
// via 3 shfl_xor (bf16x2-packed across batches) — NO smem staging, NO post-matvec
// syncthreads. Cell update in q==0 lanes (register c,h), h pair packed via
// shfl_xor(4), st.async broadcast to 4 CTAs + mbar complete_tx. One syncthreads
// per step right after the wait (orders tid0's expect_tx re-arm, near-zero skew).
#define CH_SW   0                      /* 32*256*16 = 131072 */
#define CH_HB   131072                 /* [2 parity][2 batch][512B] = 2048 */
#define CH_MB   (CH_HB + 2048)
#define CH_SMEM (CH_MB + 64)
#define CH_TXB  1024

__device__ __forceinline__ void mbar_wait_cluster(unsigned addr, unsigned parity){
    unsigned done = 0;
    while (!done){
        asm volatile(
            "{\n\t.reg .pred p;\n\t"
            "mbarrier.try_wait.parity.acquire.cluster.shared::cta.b64 p, [%1], %2, 0x989680;\n\t"
            "selp.b32 %0, 1, 0, p;\n\t}"
            : "=r"(done) : "r"(addr), "r"(parity) : "memory");
    }
}

__global__ void __cluster_dims__(4,1,1) __launch_bounds__(256, 1) k_chain(){
    uint4* sw4  = (uint4*)(chsm + CH_SW);            // [32 cb][256 tid(row-permuted)]
    uint4* hb4  = (uint4*)(chsm + CH_HB);            // [2p][2b][32]
    unsigned mb = (unsigned)__cvta_generic_to_shared(chsm + CH_MB);
    unsigned smem_base = (unsigned)__cvta_generic_to_shared(chsm);
    int tid = threadIdx.x;                           // 256
    unsigned r; asm("mov.u32 %0, %%cluster_ctarank;" : "=r"(r));
    int c = blockIdx.x >> 2;
    int b0 = 2*c, b1 = 2*c + 1;
    int w = tid >> 5, lam = tid & 31;
    int e = w*8 + (lam >> 2), q = lam & 3;
    int G = q*256 + 64*(int)r + e;                   // this thread's gate row

    // stage weights permuted: sw4[cb*256 + t2] = row G(t2), chunk cb
    for (int idx = tid; idx < 32*256; idx += 256){
        int cb2 = idx >> 8, t2 = idx & 255;
        int w2 = t2 >> 5, l2 = t2 & 31;
        int G2 = (l2 & 3)*256 + 64*(int)r + (w2*8 + (l2 >> 2));
        sw4[cb2*256 + t2] = ((const uint4*)&g_whh_bf[(size_t)G2*256])[cb2];
    }
    if (tid < 128) hb4[tid] = make_uint4(0,0,0,0);
    if (tid == 0){
        asm volatile("mbarrier.init.shared.b64 [%0], %1;" :: "r"(mb),   "r"(1) : "memory");
        asm volatile("mbarrier.init.shared.b64 [%0], %1;" :: "r"(mb+8), "r"(1) : "memory");
        asm volatile("mbarrier.arrive.expect_tx.shared::cta.b64 _, [%0], %1;"
                     :: "r"(mb),   "r"(CH_TXB) : "memory");
        asm volatile("mbarrier.arrive.expect_tx.shared::cta.b64 _, [%0], %1;"
                     :: "r"(mb+8), "r"(CH_TXB) : "memory");
    }
    __syncthreads();
    asm volatile("barrier.cluster.arrive.aligned;" ::: "memory");
    asm volatile("barrier.cluster.wait.aligned;"   ::: "memory");

    int W0 = g_wcnt[b0], W1 = g_wcnt[b1];
    int Wmax = (W0 > W1) ? W0 : W1;

    unsigned peer[4];
    #pragma unroll
    for (int qq = 0; qq < 4; qq++)
        asm("mapa.shared::cluster.u32 %0, %1, %2;" : "=r"(peer[qq]) : "r"(smem_base), "r"(qq));

    const bf16* g1p0 = &g_G1b[((size_t)b0*TLEN)*GATES + G];
    const bf16* g1p1 = &g_G1b[((size_t)b1*TLEN)*GATES + G];
    float cc0 = 0.f, hh0 = 0.f, cc1 = 0.f, hh1 = 0.f;
    int ph[2] = {0, 0};

    for (int k = 0; k < Wmax; k++){
        int p = k & 1, p2 = p ^ 1;
        if (k > 0){
            mbar_wait_cluster(mb + p*8, (unsigned)ph[p]);
            ph[p] ^= 1;
            if (tid == 0)
                asm volatile("mbarrier.arrive.expect_tx.shared::cta.b64 _, [%0], %1;"
                             :: "r"(mb + p*8), "r"(CH_TXB) : "memory");
        }
        __syncthreads();   // orders re-arm before our st.asyncs; near-zero skew here
        // issue g1 loads early (consumed after matvec; latency hidden)
        int t0 = (k < W0) ? g_bpos[b0*TLEN + k] : 0;
        int t1 = (k < W1) ? g_bpos[b1*TLEN + k] : 0;
        float g10 = __bfloat162float(g1p0[(size_t)t0*GATES]);
        float g11 = __bfloat162float(g1p1[(size_t)t1*GATES]);
        // matvec: row G, both batches, h from hb4[p]
        __nv_bfloat162 zz = __floats2bfloat162_rn(0.f, 0.f);
        __nv_bfloat162 a0a = zz, a0b = zz, a1a = zz, a1b = zz;
        const uint4* h0p = &hb4[p*64];
        const uint4* h1p = &hb4[p*64 + 32];
        #pragma unroll 8
        for (int cb2 = 0; cb2 < 32; cb2++){
            uint4 wv = sw4[cb2*256 + tid];
            uint4 h0 = h0p[cb2];
            uint4 h1 = h1p[cb2];
            const __nv_bfloat162* wp  = (const __nv_bfloat162*)&wv;
            const __nv_bfloat162* hp0 = (const __nv_bfloat162*)&h0;
            const __nv_bfloat162* hp1 = (const __nv_bfloat162*)&h1;
            a0a = __hfma2(wp[0], hp0[0], a0a); a0b = __hfma2(wp[1], hp0[1], a0b);
            a0a = __hfma2(wp[2], hp0[2], a0a); a0b = __hfma2(wp[3], hp0[3], a0b);
            a1a = __hfma2(wp[0], hp1[0], a1a); a1b = __hfma2(wp[1], hp1[1], a1b);
            a1a = __hfma2(wp[2], hp1[2], a1a); a1b = __hfma2(wp[3], hp1[3], a1b);
        }
        float2 f0a = __bfloat1622float2(a0a), f0b = __bfloat1622float2(a0b);
        float2 f1a = __bfloat1622float2(a1a), f1b = __bfloat1622float2(a1b);
        float gate0 = g10 + (f0a.x + f0a.y) + (f0b.x + f0b.y);
        float gate1 = g11 + (f1a.x + f1a.y) + (f1b.x + f1b.y);
        // pack both batches, gather i/f/g/o into q==0 lanes via 3 shfls
        __nv_bfloat162 gp = __floats2bfloat162_rn(gate0, gate1);
        unsigned gu = *(unsigned*)&gp;
        unsigned gu1 = __shfl_xor_sync(0xffffffffu, gu, 1);    // q^1
        unsigned gu2 = __shfl_xor_sync(0xffffffffu, gu, 2);    // q^2
        unsigned gu3 = __shfl_xor_sync(0xffffffffu, gu1, 2);   // q^3
        if (q == 0){
            float2 iv = __bfloat1622float2(*(__nv_bfloat162*)&gu);
            float2 fv = __bfloat1622float2(*(__nv_bfloat162*)&gu1);
            float2 gg = __bfloat1622float2(*(__nv_bfloat162*)&gu2);
            float2 ov = __bfloat1622float2(*(__nv_bfloat162*)&gu3);
            int eg = 64*(int)r + e;
            if (k < W0){
                cc0 = sigf(fv.x)*cc0 + sigf(iv.x)*tanh_fast(gg.x);
                hh0 = sigf(ov.x)*tanh_fast(cc0);
                g_Hwb[((size_t)(b0*TLEN + k))*RNNH + eg] = __float2bfloat16(hh0);
                g_Cw [((size_t)(b0*TLEN + k))*RNNH + eg] = cc0;
            }
            if (k < W1){
                cc1 = sigf(fv.y)*cc1 + sigf(iv.y)*tanh_fast(gg.y);
                hh1 = sigf(ov.y)*tanh_fast(cc1);
                g_Hwb[((size_t)(b1*TLEN + k))*RNNH + eg] = __float2bfloat16(hh1);
                g_Cw [((size_t)(b1*TLEN + k))*RNNH + eg] = cc1;
            }
        }
        // pack h pairs (e even with e+1 from lane+4) and broadcast
        float h0o = __shfl_xor_sync(0xffffffffu, hh0, 4);
        float h1o = __shfl_xor_sync(0xffffffffu, hh1, 4);
        if ((lam & 7) == 0){
            __nv_bfloat162 pk0 = __floats2bfloat162_rn(hh0, h0o);
            __nv_bfloat162 pk1 = __floats2bfloat162_rn(hh1, h1o);
            unsigned v0 = *(unsigned*)&pk0;
            unsigned v1 = *(unsigned*)&pk1;
            int widx = 32*(int)r + w*4 + (lam >> 3);   // pair index within batch
            unsigned woff0 = (unsigned)(CH_HB + p2*1024 +       widx*4);
            unsigned woff1 = (unsigned)(CH_HB + p2*1024 + 512 + widx*4);
            unsigned moff = (unsigned)(CH_MB + p2*8);
            #pragma unroll
            for (int qq = 0; qq < 4; qq++){
                asm volatile("st.async.shared::cluster.mbarrier::complete_tx::bytes.b32 "
                             "[%0], %1, [%2];"
                             :: "r"(peer[qq] + woff0), "r"(v0), "r"(peer[qq] + moff)
                             : "memory");
                asm volatile("st.async.shared::cluster.mbarrier::complete_tx::bytes.b32 "
                             "[%0], %1, [%2];"
                             :: "r"(peer[qq] + woff1), "r"(v1), "r"(peer[qq] + moff)
                             : "memory");
            }
        }
    }
    asm volatile("barrier.cluster.arrive.aligned;" ::: "memory");
    asm volatile("barrier.cluster.wait.aligned;"   ::: "memory");
}

// ---------------- L5: parallel per-step LSTM cell apply --------------------------
__global__ void k_apply(){
    int m = blockIdx.x;
    int d = threadIdx.x;          // 256
    int b = m >> 9;
    int j = g_cidx[m];
    size_t gbase = (size_t)m*GATES;
    float iv = __bfloat162float(g_G1b[gbase +       d]);
    float fv = __bfloat162float(g_G1b[gbase + 256 + d]);
    float gv = __bfloat162float(g_G1b[gbase + 512 + d]);
    float ov = __bfloat162float(g_G1b[gbase + 768 + d]);
    float cprev = 0.f;
    if (j >= 0){
        size_t hbase = (size_t)(b*TLEN + j)*GATES;
        iv += __bfloat162float(g_H2b[hbase +       d]);
        fv += __bfloat162float(g_H2b[hbase + 256 + d]);
        gv += __bfloat162float(g_H2b[hbase + 512 + d]);
        ov += __bfloat162float(g_H2b[hbase + 768 + d]);
        cprev = g_Cw[(size_t)(b*TLEN + j)*RNNH + d];
    }
    float cc = sigf(fv)*cprev + sigf(iv)*tanh_fast(gv);
    g_hsb[(size_t)m*RNNH + d] = __float2bfloat16(sigf(ov)*tanh_fast(cc));
}

// ---------------- L6: logits mma GEMM ([hs|enc] @ lw^T) + fused log_softmax ------
#define LG_SMEM (128*132*4)
__global__ void __launch_bounds__(256) k_logits(const int* __restrict__ lengths,
                                                float* __restrict__ out, int dup){
    __shared__ bf16 sA[128*SSTR];
    __shared__ bf16 sW[128*SSTR];
    float* sC = (float*)chsm;    // [128][132]
    int row0 = blockIdx.x * 128;
    int tid = threadIdx.x;
    int lane = tid & 31, wid = tid >> 5;
    int warp_m = wid & 3, warp_n = wid >> 2;
    int lrow = tid >> 2, lseg = tid & 3;

    unsigned sAb = (unsigned)__cvta_generic_to_shared(sA);
    unsigned sWb = (unsigned)__cvta_generic_to_shared(sW);
    unsigned aAddr = sAb + (unsigned)(((warp_m*32 + (lane&15))*SSTR + (lane>>4)*8)*2);
    unsigned bAddr = sWb + (unsigned)(((warp_n*64 + ((lane>>4)<<3) + (lane&7))*SSTR
                                      + ((lane>>3)&1)*8)*2);
    float acc[2][8][4];
    #pragma unroll
    for (int mi=0;mi<2;mi++)
        #pragma unroll
        for (int j=0;j<8;j++)
            #pragma unroll
            for (int q=0;q<4;q++) acc[mi][j][q] = 0.f;

    for (int k0 = 0; k0 < 768; k0 += 32){
        int kk = k0 + lseg*8;
        int m0 = row0 + lrow;
        uint4 a0, a1;
        if (kk < 256){
            a0 = *(const uint4*)&g_hsb[(size_t)m0*RNNH + kk];
            a1 = *(const uint4*)&g_hsb[(size_t)(m0+64)*RNNH + kk];
        } else {
            a0 = *(const uint4*)&g_encb[(size_t)m0*ENCD + kk - 256];
            a1 = *(const uint4*)&g_encb[(size_t)(m0+64)*ENCD + kk - 256];
        }
        uint4 w0 = *(const uint4*)&g_lwb[(size_t)lrow*768 + kk];
        uint4 w1 = *(const uint4*)&g_lwb[(size_t)(lrow+64)*768 + kk];
        *(uint4*)&sA[lrow*SSTR + lseg*8]      = a0;
        *(uint4*)&sA[(lrow+64)*SSTR + lseg*8] = a1;
        *(uint4*)&sW[lrow*SSTR + lseg*8]      = w0;
        *(uint4*)&sW[(lrow+64)*SSTR + lseg*8] = w1;
        __syncthreads();
        #pragma unroll
        for (int ks = 0; ks < 32; ks += 16){
            unsigned af[2][4], bfg[4][4];
            #pragma unroll
            for (int mi=0;mi<2;mi++)
                ldm_x4(aAddr + mi*16*SSTR*2 + ks*2, af[mi][0],af[mi][1],af[mi][2],af[mi][3]);
            #pragma unroll
            for (int p=0;p<4;p++)
                ldm_x4(bAddr + p*16*SSTR*2 + ks*2, bfg[p][0],bfg[p][1],bfg[p][2],bfg[p][3]);
            #pragma unroll
            for (int mi=0;mi<2;mi++)
                #pragma unroll
                for (int j=0;j<8;j++)
                    mma16816(acc[mi][j], af[mi], &bfg[j>>1][(j&1)*2]);
        }
        __syncthreads();
    }
    #pragma unroll
    for (int mi=0;mi<2;mi++)
        #pragma unroll
        for (int j=0;j<8;j++)
            #pragma unroll
            for (int q=0;q<2;q++){
                int rl = warp_m*32 + mi*16 + q*8 + (lane>>2);
                int cl = warp_n*64 + j*8 + (lane&3)*2;
                *(float2*)&sC[rl*132 + cl] = make_float2(acc[mi][j][q*2], acc[mi][j][q*2+1]);
            }
    __syncthreads();
    for (int rr = 0; rr < 16; rr++){
        int rl = wid*16 + rr;
        int m = row0 + rl;
        int b = m >> 9, t = m & 511;
        int L = lengths[b];
        float v[4];
        float vmax = -3.0e38f;
        #pragma unroll
        for (int u=0;u<4;u++){
            int n = lane + u*32;
            float x = sC[rl*132 + n];
            if (t == 0 && n == 0) x = -1e30f;
            if (t >= L) x = 0.f;
            v[u] = x;
            vmax = fmaxf(vmax, x);
        }
        #pragma unroll
        for (int d=16; d>=1; d>>=1) vmax = fmaxf(vmax, __shfl_xor_sync(0xffffffffu, vmax, d, 32));
        float ssum = 0.f;
        #pragma unroll
        for (int u=0;u<4;u++) ssum += expf(v[u] - vmax);
        #pragma unroll
        for (int d=16; d>=1; d>>=1) ssum += __shfl_xor_sync(0xffffffffu, ssum, d, 32);
        float lse = vmax + logf(ssum);
        #pragma unroll
        for (int u=0;u<4;u++){
            int n = lane + u*32;
            size_t idx = (size_t)m*LABEL + n;
            float res = v[u] - lse;
            out[idx] = res;
            if (dup) out[(size_t)OUTN + idx] = res;
        }
    }
}

// ---------------- launcher -------------------------------------------------------
extern "C" void kernel_launch(void* const* d_in, const int* in_sizes, int n_in,
                              void* d_out, int out_size){
    const float* enc  = (const float*)d_in[0];
    const int*   bnd  = (const int*)  d_in[1];
    const int*   pos  = (const int*)  d_in[2];
    const int*   len  = (const int*)  d_in[3];
    const float* w_ih = (const float*)d_in[4];
    const float* w_hh = (const float*)d_in[5];
    const float* b_ih = (const float*)d_in[6];
    const float* b_hh = (const float*)d_in[7];
    const float* ptab = (const float*)d_in[8];
    const float* lw   = (const float*)d_in[9];
    const float* cw   = (const float*)d_in[10];
    const float* cb   = (const float*)d_in[11];
    float* out = (float*)d_out;
    int dup = (out_size >= 2*OUTN) ? 1 : 0;

    void* p;
    cudaGetSymbolAddress(&p, g_Hwb);    bf16* Hwb  = (bf16*)p;
    cudaGetSymbolAddress(&p, g_H2b);    bf16* H2b  = (bf16*)p;
    cudaGetSymbolAddress(&p, g_whh_bf); bf16* whhb = (bf16*)p;

    cudaFuncSetAttribute(k_zg1,    cudaFuncAttributeMaxDynamicSharedMemorySize, ZG_SMEM);
    cudaFuncSetAttribute(k_chain,  cudaFuncAttributeMaxDynamicSharedMemorySize, CH_SMEM);
    cudaFuncSetAttribute(k_logits, cudaFuncAttributeMaxDynamicSharedMemorySize, LG_SMEM);

    // launch 0: conversions + boundary scan
    k_conv_scan<<<CONV_BLOCKS + 8, 256>>>(enc, cw, w_ih, w_hh, lw, bnd);
    // launch 1: zin build
    k_build_zin<<<dim3(2, BATCH), 512>>>(enc, bnd, pos, ptab);
    // launch 2: fused z + G1 GEMM
    k_zg1<<<MROWS/128, 256, ZG_SMEM>>>(cb, b_ih, b_hh);
    // launch 3 (ncu lands here): carry chain (in-warp gate gather)
    k_chain<<<(BATCH/2)*4, 256, CH_SMEM>>>();
    // launch 4: H2 = Hw @ w_hh^T (ragged skip)
    k_gemm_mma<2><<<dim3(GATES/128, MROWS/128), 256>>>(Hwb, whhb, H2b, RNNH, GATES,
                                                        nullptr, nullptr);
    // launch 5: parallel per-step LSTM outputs
    k_apply<<<MROWS, 256>>>();
    // launch 6: logits + masking + log_softmax
    k_logits<<<MROWS/128, 256, LG_SMEM>>>(len, out, dup);
}

// round 15
// speedup vs baseline: 1.0059x; 1.0059x over previous
#include <cuda_runtime.h>
#include <cuda_bf16.h>
#include <cstdint>
#include <math.h>

#define BATCH 64
#define TLEN  512
#define RNNH  256
#define ENCD  512
#define ZK    640
#define GATES 1024
#define LABEL 128
#define MROWS (BATCH*TLEN)          /* 32768 */
#define OUTN  (4194304)             /* MROWS*LABEL */

typedef __nv_bfloat16 bf16;

// ---------------- scratch (device globals; no allocation allowed) ----------------
__device__ __align__(16) bf16  g_zinb[(size_t)MROWS*ZK];    // [B*T,640] pe|pool (bf16)
__device__ __align__(16) bf16  g_G1b[(size_t)MROWS*GATES];  // z@w_ih^T + b_ih + b_hh (bf16)
__device__ __align__(16) bf16  g_Hwb[(size_t)MROWS*RNNH];   // per-word carry h_j (bf16)
__device__ __align__(16) float g_Cw [(size_t)MROWS*RNNH];   // per-word carry c_j (fp32)
__device__ __align__(16) bf16  g_H2b[(size_t)MROWS*GATES];  // Hw@w_hh^T (bf16)
__device__ __align__(16) bf16  g_hsb[(size_t)MROWS*RNNH];   // per-step LSTM output (bf16)
__device__ __align__(16) bf16  g_encb[(size_t)MROWS*ENCD];  // encoder_out bf16
__device__ __align__(16) bf16  g_cwb [RNNH*ZK];
__device__ __align__(16) bf16  g_wihb[GATES*RNNH];
__device__ __align__(16) bf16  g_whh_bf[GATES*RNNH];
__device__ __align__(16) bf16  g_lwb [LABEL*768];
__device__ int   g_svec[MROWS];
__device__ int   g_cidx[MROWS];
__device__ int   g_bpos[MROWS];
__device__ int   g_wcnt[BATCH];

// fast activations: tanh.approx-based (err ~2^-10, << bf16 gate noise)
__device__ __forceinline__ float tanh_fast(float x){
    float y; asm("tanh.approx.f32 %0, %1;" : "=f"(y) : "f"(x));
    return y;
}
__device__ __forceinline__ float sigf(float x){
    return fmaf(0.5f, tanh_fast(0.5f*x), 0.5f);
}

// ---------------- L0: all f32->bf16 conversions + ballot boundary scan -----------
#define N_ENC4 (MROWS*ENCD/4)
#define N_CW4  (RNNH*ZK/4)
#define N_W4   (GATES*RNNH/4)
#define N_LW4  (LABEL*768/4)
#define N_ALL4 (N_ENC4 + N_CW4 + N_W4 + N_W4 + N_LW4)
#define CONV_BLOCKS ((N_ALL4 + 255)/256)

__device__ __forceinline__ void cvt4(const float* s, bf16* d, long i){
    float4 v = *(const float4*)(s + i*4);
    __nv_bfloat162* o = (__nv_bfloat162*)(d + i*4);
    o[0] = __floats2bfloat162_rn(v.x, v.y);
    o[1] = __floats2bfloat162_rn(v.z, v.w);
}
__global__ void k_conv_scan(const float* __restrict__ enc, const float* __restrict__ cw,
                            const float* __restrict__ wih, const float* __restrict__ whh,
                            const float* __restrict__ lw, const int* __restrict__ bnd){
    if (blockIdx.x < CONV_BLOCKS){
        long i = (long)blockIdx.x*256 + threadIdx.x;
        if (i < N_ENC4){ cvt4(enc, g_encb, i); return; }
        i -= N_ENC4;
        if (i < N_CW4){ cvt4(cw, g_cwb, i); return; }
        i -= N_CW4;
        if (i < N_W4){ cvt4(wih, g_wihb, i); return; }
        i -= N_W4;
        if (i < N_W4){ cvt4(whh, g_whh_bf, i); return; }
        i -= N_W4;
        if (i < N_LW4){ cvt4(lw, g_lwb, i); }
    } else {
        int warp = (blockIdx.x - CONV_BLOCKS)*8 + (threadIdx.x >> 5);  // 0..63
        int lane = threadIdx.x & 31;
        if (warp >= BATCH) return;
        int base = warp*TLEN;
        int cnt = 0, last = 0;
        for (int c = 0; c < TLEN/32; c++){
            int t = c*32 + lane;
            int bv = bnd[base + t];
            unsigned m = __ballot_sync(0xffffffffu, bv == 1);
            unsigned mlt = m & ((1u << lane) - 1u);
            int sv = mlt ? (c*32 + 31 - __clz(mlt)) : last;
            g_svec[base + t] = sv;
            g_cidx[base + t] = cnt + __popc(mlt) - 1;
            if (bv == 1) g_bpos[base + cnt + __popc(mlt)] = t;
            cnt += __popc(m);
            last = m ? (c*32 + 31 - __clz(m)) : last;
        }
        if (lane == 0) g_wcnt[warp] = cnt;
    }
}

// ---------------- L1: build zin = [pos_emb(128) | running word mean(512)] --------
__global__ void __launch_bounds__(512) k_build_zin(
        const float* __restrict__ enc, const int* __restrict__ bnd,
        const int* __restrict__ pos, const float* __restrict__ ptab){
    int b = blockIdx.y;
    int tid = threadIdx.x;
    if (blockIdx.x == 0){
        int dim = tid & 127, tq = tid >> 7;
        for (int t = tq; t < TLEN; t += 4){
            int s = g_svec[b*TLEN + t];
            int p = pos[b*TLEN + s];
            g_zinb[(size_t)(b*TLEN + t)*ZK + dim] = __float2bfloat16(ptab[p*128 + dim]);
        }
    } else {
        int dim = tid;  // 0..511
        float acc = 0.f;
        for (int t = 0; t < TLEN; t += 4){
            float e[4]; int s[4], bb[4];
            #pragma unroll
            for (int j = 0; j < 4; j++){
                e[j]  = enc[(size_t)(b*TLEN + t + j)*ENCD + dim];
                s[j]  = g_svec[b*TLEN + t + j];
                bb[j] = bnd[b*TLEN + t + j];
            }
            #pragma unroll
            for (int j = 0; j < 4; j++){
                int wl = (t + j) - s[j]; if (wl < 1) wl = 1;
                g_zinb[(size_t)(b*TLEN + t + j)*ZK + 128 + dim] =
                    __float2bfloat16(acc / (float)wl);
                acc = (bb[j] == 1) ? e[j] : (acc + e[j]);
            }
        }
    }
}

// ================= mma primitives =================================================
#define SSTR 40  /* smem row stride in bf16 elems (80B, conflict-free for ldmatrix) */

__device__ __forceinline__ void ldm_x4(unsigned addr, unsigned& r0, unsigned& r1,
                                       unsigned& r2, unsigned& r3){
    asm volatile("ldmatrix.sync.aligned.m8n8.x4.shared.b16 {%0,%1,%2,%3}, [%4];"
                 : "=r"(r0), "=r"(r1), "=r"(r2), "=r"(r3) : "r"(addr));
}
__device__ __forceinline__ void mma16816(float* c, const unsigned* a, const unsigned* b){
    asm volatile("mma.sync.aligned.m16n8k16.row.col.f32.bf16.bf16.f32 "
                 "{%0,%1,%2,%3}, {%4,%5,%6,%7}, {%8,%9}, {%0,%1,%2,%3};"
                 : "+f"(c[0]), "+f"(c[1]), "+f"(c[2]), "+f"(c[3])
                 : "r"(a[0]), "r"(a[1]), "r"(a[2]), "r"(a[3]), "r"(b[0]), "r"(b[1]));
}

// ---------------- L2: fused z + G1 GEMM ------------------------------------------
#define ZS_OFF   0
#define ZS_TILE  (128*SSTR*2)          /* 10240 B per k-tile */
#define ZG_SA    (8*ZS_TILE)           /* 81920 */
#define ZG_SW    (ZG_SA + 128*SSTR*2)  /* 92160 */
#define ZG_SMEM  (ZG_SW + 128*SSTR*2)  /* 102400 */
extern __shared__ char chsm[];

__global__ void __launch_bounds__(256) k_zg1(const float* __restrict__ cb,
                                             const float* __restrict__ bih,
                                             const float* __restrict__ bhh){
    bf16* zS = (bf16*)(chsm + ZS_OFF);
    bf16* sA = (bf16*)(chsm + ZG_SA);
    bf16* sW = (bf16*)(chsm + ZG_SW);
    int row0 = blockIdx.x * 128;
    int tid = threadIdx.x;
    int lane = tid & 31, wid = tid >> 5;
    int warp_m = wid & 3, warp_n = wid >> 2;
    int lrow = tid >> 2, lseg = tid & 3;

    unsigned sAb = (unsigned)__cvta_generic_to_shared(sA);
    unsigned sWb = (unsigned)__cvta_generic_to_shared(sW);
    unsigned zSb = (unsigned)__cvta_generic_to_shared(zS);
    unsigned aOff = (unsigned)(((warp_m*32 + (lane&15))*SSTR + (lane>>4)*8)*2);
    unsigned bOff = (unsigned)(((warp_n*64 + ((lane>>4)<<3) + (lane&7))*SSTR
                               + ((lane>>3)&1)*8)*2);

    for (int ch = 0; ch < 2; ch++){
        int col0 = ch*128;
        const bf16* Ap = g_zinb + (size_t)(row0 + lrow)*ZK + lseg*8;
        const bf16* Wp = g_cwb  + (size_t)(col0 + lrow)*ZK + lseg*8;
        float acc[2][8][4];
        #pragma unroll
        for (int mi=0;mi<2;mi++)
            #pragma unroll
            for (int j=0;j<8;j++)
                #pragma unroll
                for (int q=0;q<4;q++) acc[mi][j][q] = 0.f;
        uint4 a0 = *(const uint4*)(Ap);
        uint4 a1 = *(const uint4*)(Ap + (size_t)64*ZK);
        uint4 w0 = *(const uint4*)(Wp);
        uint4 w1 = *(const uint4*)(Wp + (size_t)64*ZK);
        for (int k0 = 0; k0 < ZK; k0 += 32){
            *(uint4*)&sA[lrow*SSTR + lseg*8]       = a0;
            *(uint4*)&sA[(lrow+64)*SSTR + lseg*8]  = a1;
            *(uint4*)&sW[lrow*SSTR + lseg*8]       = w0;
            *(uint4*)&sW[(lrow+64)*SSTR + lseg*8]  = w1;
            __syncthreads();
            if (k0 + 32 < ZK){
                a0 = *(const uint4*)(Ap + k0 + 32);
                a1 = *(const uint4*)(Ap + (size_t)64*ZK + k0 + 32);
                w0 = *(const uint4*)(Wp + k0 + 32);
                w1 = *(const uint4*)(Wp + (size_t)64*ZK + k0 + 32);
            }
            #pragma unroll
            for (int ks = 0; ks < 32; ks += 16){
                unsigned af[2][4], bfg[4][4];
                #pragma unroll
                for (int mi=0;mi<2;mi++)
                    ldm_x4(sAb + aOff + mi*16*SSTR*2 + ks*2,
                           af[mi][0],af[mi][1],af[mi][2],af[mi][3]);
                #pragma unroll
                for (int p=0;p<4;p++)
                    ldm_x4(sWb + bOff + p*16*SSTR*2 + ks*2,
                           bfg[p][0],bfg[p][1],bfg[p][2],bfg[p][3]);
                #pragma unroll
                for (int mi=0;mi<2;mi++)
                    #pragma unroll
                    for (int j=0;j<8;j++)
                        mma16816(acc[mi][j], af[mi], &bfg[j>>1][(j&1)*2]);
            }
            __syncthreads();
        }
        #pragma unroll
        for (int mi=0;mi<2;mi++){
            #pragma unroll
            for (int j=0;j<8;j++){
                #pragma unroll
                for (int q=0;q<2;q++){
                    int ml = warp_m*32 + mi*16 + q*8 + (lane>>2);
                    int n  = col0 + warp_n*64 + j*8 + (lane&3)*2;
                    float v0 = tanh_fast(acc[mi][j][q*2+0] + cb[n]);
                    float v1 = tanh_fast(acc[mi][j][q*2+1] + cb[n+1]);
                    if (((row0 + ml) & 511) == 0){ v0 = 0.f; v1 = 0.f; }
                    int kt = n >> 5, kk = n & 31;
                    *(__nv_bfloat162*)&zS[kt*128*SSTR + ml*SSTR + kk] =
                        __floats2bfloat162_rn(v0, v1);
                }
            }
        }
        __syncthreads();
    }

    for (int nt = 0; nt < 8; nt++){
        int col0 = nt*128;
        const bf16* Wp = g_wihb + (size_t)(col0 + lrow)*RNNH + lseg*8;
        float acc[2][8][4];
        #pragma unroll
        for (int mi=0;mi<2;mi++)
            #pragma unroll
            for (int j=0;j<8;j++)
                #pragma unroll
                for (int q=0;q<4;q++) acc[mi][j][q] = 0.f;
        uint4 w0 = *(const uint4*)(Wp);
        uint4 w1 = *(const uint4*)(Wp + (size_t)64*RNNH);
        for (int kt = 0; kt < 8; kt++){
            *(uint4*)&sW[lrow*SSTR + lseg*8]       = w0;
            *(uint4*)&sW[(lrow+64)*SSTR + lseg*8]  = w1;
            __syncthreads();
            if (kt < 7){
                w0 = *(const uint4*)(Wp + (kt+1)*32);
                w1 = *(const uint4*)(Wp + (size_t)64*RNNH + (kt+1)*32);
            }
            unsigned zBase = zSb + kt*ZS_TILE;
            #pragma unroll
            for (int ks = 0; ks < 32; ks += 16){
                unsigned af[2][4], bfg[4][4];
                #pragma unroll
                for (int mi=0;mi<2;mi++)
                    ldm_x4(zBase + aOff + mi*16*SSTR*2 + ks*2,
                           af[mi][0],af[mi][1],af[mi][2],af[mi][3]);
                #pragma unroll
                for (int p=0;p<4;p++)
                    ldm_x4(sWb + bOff + p*16*SSTR*2 + ks*2,
                           bfg[p][0],bfg[p][1],bfg[p][2],bfg[p][3]);
                #pragma unroll
                for (int mi=0;mi<2;mi++)
                    #pragma unroll
                    for (int j=0;j<8;j++)
                        mma16816(acc[mi][j], af[mi], &bfg[j>>1][(j&1)*2]);
            }
            __syncthreads();
        }
        #pragma unroll
        for (int mi=0;mi<2;mi++){
            #pragma unroll
            for (int j=0;j<8;j++){
                #pragma unroll
                for (int q=0;q<2;q++){
                    int m = row0 + warp_m*32 + mi*16 + q*8 + (lane>>2);
                    int n = col0 + warp_n*64 + j*8 + (lane&3)*2;
                    float v0 = acc[mi][j][q*2+0] + bih[n]   + bhh[n];
                    float v1 = acc[mi][j][q*2+1] + bih[n+1] + bhh[n+1];
                    *(__nv_bfloat162*)&g_G1b[(size_t)m*GATES + n] =
                        __floats2bfloat162_rn(v0, v1);
                }
            }
        }
    }
}

// ---------------- generic bf16 mma GEMM (used for H2, EPI 2 only) -----------------
template<int EPI>
__global__ void __launch_bounds__(256) k_gemm_mma(
        const bf16* __restrict__ A, const bf16* __restrict__ W,
        bf16* __restrict__ Cb, int K, int N,
        const float* __restrict__ bias1, const float* __restrict__ bias2){
    int row0 = blockIdx.y * 128;
    int col0 = blockIdx.x * 128;
    if (EPI == 2){
        int b = row0 >> 9;
        if ((row0 & 511) >= g_wcnt[b]) return;
    }
    __shared__ bf16 sA[128*SSTR];
    __shared__ bf16 sW[128*SSTR];
    int tid = threadIdx.x;
    int lane = tid & 31, wid = tid >> 5;
    int warp_m = wid & 3, warp_n = wid >> 2;
    int lrow = tid >> 2, lseg = tid & 3;

    const bf16* Ap = A + (size_t)(row0 + lrow)*K + lseg*8;
    const bf16* Wp = W + (size_t)(col0 + lrow)*K + lseg*8;

    unsigned sAb = (unsigned)__cvta_generic_to_shared(sA);
    unsigned sWb = (unsigned)__cvta_generic_to_shared(sW);
    unsigned aAddr = sAb + (unsigned)(((warp_m*32 + (lane&15))*SSTR + (lane>>4)*8)*2);
    unsigned bAddr = sWb + (unsigned)(((warp_n*64 + ((lane>>4)<<3) + (lane&7))*SSTR
                                      + ((lane>>3)&1)*8)*2);
    float acc[2][8][4];
    #pragma unroll
    for (int mi=0;mi<2;mi++)
        #pragma unroll
        for (int j=0;j<8;j++)
            #pragma unroll
            for (int q=0;q<4;q++) acc[mi][j][q] = 0.f;

    uint4 a0 = *(const uint4*)(Ap);
    uint4 a1 = *(const uint4*)(Ap + (size_t)64*K);
    uint4 w0 = *(const uint4*)(Wp);
    uint4 w1 = *(const uint4*)(Wp + (size_t)64*K);

    for (int k0 = 0; k0 < K; k0 += 32){
        *(uint4*)&sA[lrow*SSTR + lseg*8]       = a0;
        *(uint4*)&sA[(lrow+64)*SSTR + lseg*8]  = a1;
        *(uint4*)&sW[lrow*SSTR + lseg*8]       = w0;
        *(uint4*)&sW[(lrow+64)*SSTR + lseg*8]  = w1;
        __syncthreads();
        if (k0 + 32 < K){
            a0 = *(const uint4*)(Ap + k0 + 32);
            a1 = *(const uint4*)(Ap + (size_t)64*K + k0 + 32);
            w0 = *(const uint4*)(Wp + k0 + 32);
            w1 = *(const uint4*)(Wp + (size_t)64*K + k0 + 32);
        }
        #pragma unroll
        for (int ks = 0; ks < 32; ks += 16){
            unsigned af[2][4], bfg[4][4];
            #pragma unroll
            for (int mi=0;mi<2;mi++)
                ldm_x4(aAddr + mi*16*SSTR*2 + ks*2, af[mi][0],af[mi][1],af[mi][2],af[mi][3]);
            #pragma unroll
            for (int p=0;p<4;p++)
                ldm_x4(bAddr + p*16*SSTR*2 + ks*2, bfg[p][0],bfg[p][1],bfg[p][2],bfg[p][3]);
            #pragma unroll
            for (int mi=0;mi<2;mi++)
                #pragma unroll
                for (int j=0;j<8;j++)
                    mma16816(acc[mi][j], af[mi], &bfg[j>>1][(j&1)*2]);
        }
        __syncthreads();
    }
    #pragma unroll
    for (int mi=0;mi<2;mi++){
        #pragma unroll
        for (int j=0;j<8;j++){
            #pragma unroll
            for (int q=0;q<2;q++){
                int m = row0 + warp_m*32 + mi*16 + q*8 + (lane>>2);
                int n = col0 + warp_n*64 + j*8 + (lane&3)*2;
                *(__nv_bfloat162*)&Cb[(size_t)m*N + n] =
                    __floats2bfloat162_rn(acc[mi][j][q*2+0], acc[mi][j][q*2+1]);
            }
        }
    }
}

// ---------------- L3: cluster-4 chain, in-warp gate gather, st.async exchange ----
// 32 clusters x 4 CTAs, 2 batches each, 256 threads. Lane mapping: warp w, lane λ:
// element e = w*8 + (λ>>2), gate q = λ&3, global row G = q*256 + 64r + e. Each
// thread matvecs its row for BOTH batches (weights read once). Gates gathered
// via 3 shfl_xor (bf16x2-packed across batches) — NO smem staging, NO post-matvec
// syncthreads. Cell update in q==0 lanes (register c,h), h pair packed via
// shfl_xor(4), st.async broadcast to 4 CTAs + mbar complete_tx. One syncthreads
// per step right after the wait (orders tid0's expect_tx re-arm, near-zero skew).
#define CH_SW   0                      /* 32*256*16 = 131072 */
#define CH_HB   131072                 /* [2 parity][2 batch][512B] = 2048 */
#define CH_MB   (CH_HB + 2048)
#define CH_SMEM (CH_MB + 64)
#define CH_TXB  1024

__device__ __forceinline__ void mbar_wait_cluster(unsigned addr, unsigned parity){
    unsigned done = 0;
    while (!done){
        asm volatile(
            "{\n\t.reg .pred p;\n\t"
            "mbarrier.try_wait.parity.acquire.cluster.shared::cta.b64 p, [%1], %2, 0x989680;\n\t"
            "selp.b32 %0, 1, 0, p;\n\t}"
            : "=r"(done) : "r"(addr), "r"(parity) : "memory");
    }
}

__global__ void __cluster_dims__(4,1,1) __launch_bounds__(256, 1) k_chain(){
    uint4* sw4  = (uint4*)(chsm + CH_SW);            // [32 cb][256 tid(row-permuted)]
    uint4* hb4  = (uint4*)(chsm + CH_HB);            // [2p][2b][32]
    unsigned mb = (unsigned)__cvta_generic_to_shared(chsm + CH_MB);
    unsigned smem_base = (unsigned)__cvta_generic_to_shared(chsm);
    int tid = threadIdx.x;                           // 256
    unsigned r; asm("mov.u32 %0, %%cluster_ctarank;" : "=r"(r));
    int c = blockIdx.x >> 2;
    int b0 = 2*c, b1 = 2*c + 1;
    int w = tid >> 5, lam = tid & 31;
    int e = w*8 + (lam >> 2), q = lam & 3;
    int G = q*256 + 64*(int)r + e;                   // this thread's gate row

    // stage weights permuted: sw4[cb*256 + t2] = row G(t2), chunk cb
    for (int idx = tid; idx < 32*256; idx += 256){
        int cb2 = idx >> 8, t2 = idx & 255;
        int w2 = t2 >> 5, l2 = t2 & 31;
        int G2 = (l2 & 3)*256 + 64*(int)r + (w2*8 + (l2 >> 2));
        sw4[cb2*256 + t2] = ((const uint4*)&g_whh_bf[(size_t)G2*256])[cb2];
    }
    if (tid < 128) hb4[tid] = make_uint4(0,0,0,0);
    if (tid == 0){
        asm volatile("mbarrier.init.shared.b64 [%0], %1;" :: "r"(mb),   "r"(1) : "memory");
        asm volatile("mbarrier.init.shared.b64 [%0], %1;" :: "r"(mb+8), "r"(1) : "memory");
        asm volatile("mbarrier.arrive.expect_tx.shared::cta.b64 _, [%0], %1;"
                     :: "r"(mb),   "r"(CH_TXB) : "memory");
        asm volatile("mbarrier.arrive.expect_tx.shared::cta.b64 _, [%0], %1;"
                     :: "r"(mb+8), "r"(CH_TXB) : "memory");
    }
    __syncthreads();
    asm volatile("barrier.cluster.arrive.aligned;" ::: "memory");
    asm volatile("barrier.cluster.wait.aligned;"   ::: "memory");

    int W0 = g_wcnt[b0], W1 = g_wcnt[b1];
    int Wmax = (W0 > W1) ? W0 : W1;

    unsigned peer[4];
    #pragma unroll
    for (int qq = 0; qq < 4; qq++)
        asm("mapa.shared::cluster.u32 %0, %1, %2;" : "=r"(peer[qq]) : "r"(smem_base), "r"(qq));

    const bf16* g1p0 = &g_G1b[((size_t)b0*TLEN)*GATES + G];
    const bf16* g1p1 = &g_G1b[((size_t)b1*TLEN)*GATES + G];
    float cc0 = 0.f, hh0 = 0.f, cc1 = 0.f, hh1 = 0.f;
    int ph[2] = {0, 0};

    for (int k = 0; k < Wmax; k++){
        int p = k & 1, p2 = p ^ 1;
        if (k > 0){
            mbar_wait_cluster(mb + p*8, (unsigned)ph[p]);
            ph[p] ^= 1;
            if (tid == 0)
                asm volatile("mbarrier.arrive.expect_tx.shared::cta.b64 _, [%0], %1;"
                             :: "r"(mb + p*8), "r"(CH_TXB) : "memory");
        }
        __syncthreads();   // orders re-arm before our st.asyncs; near-zero skew here
        // issue g1 loads early (consumed after matvec; latency hidden)
        int t0 = (k < W0) ? g_bpos[b0*TLEN + k] : 0;
        int t1 = (k < W1) ? g_bpos[b1*TLEN + k] : 0;
        float g10 = __bfloat162float(g1p0[(size_t)t0*GATES]);
        float g11 = __bfloat162float(g1p1[(size_t)t1*GATES]);
        // matvec: row G, both batches, h from hb4[p]
        __nv_bfloat162 zz = __floats2bfloat162_rn(0.f, 0.f);
        __nv_bfloat162 a0a = zz, a0b = zz, a1a = zz, a1b = zz;
        const uint4* h0p = &hb4[p*64];
        const uint4* h1p = &hb4[p*64 + 32];
        #pragma unroll 8
        for (int cb2 = 0; cb2 < 32; cb2++){
            uint4 wv = sw4[cb2*256 + tid];
            uint4 h0 = h0p[cb2];
            uint4 h1 = h1p[cb2];
            const __nv_bfloat162* wp  = (const __nv_bfloat162*)&wv;
            const __nv_bfloat162* hp0 = (const __nv_bfloat162*)&h0;
            const __nv_bfloat162* hp1 = (const __nv_bfloat162*)&h1;
            a0a = __hfma2(wp[0], hp0[0], a0a); a0b = __hfma2(wp[1], hp0[1], a0b);
            a0a = __hfma2(wp[2], hp0[2], a0a); a0b = __hfma2(wp[3], hp0[3], a0b);
            a1a = __hfma2(wp[0], hp1[0], a1a); a1b = __hfma2(wp[1], hp1[1], a1b);
            a1a = __hfma2(wp[2], hp1[2], a1a); a1b = __hfma2(wp[3], hp1[3], a1b);
        }
        float2 f0a = __bfloat1622float2(a0a), f0b = __bfloat1622float2(a0b);
        float2 f1a = __bfloat1622float2(a1a), f1b = __bfloat1622float2(a1b);
        float gate0 = g10 + (f0a.x + f0a.y) + (f0b.x + f0b.y);
        float gate1 = g11 + (f1a.x + f1a.y) + (f1b.x + f1b.y);
        // pack both batches, gather i/f/g/o into q==0 lanes via 3 shfls
        __nv_bfloat162 gp = __floats2bfloat162_rn(gate0, gate1);
        unsigned gu = *(unsigned*)&gp;
        unsigned gu1 = __shfl_xor_sync(0xffffffffu, gu, 1);    // q^1
        unsigned gu2 = __shfl_xor_sync(0xffffffffu, gu, 2);    // q^2
        unsigned gu3 = __shfl_xor_sync(0xffffffffu, gu1, 2);   // q^3
        if (q == 0){
            float2 iv = __bfloat1622float2(*(__nv_bfloat162*)&gu);
            float2 fv = __bfloat1622float2(*(__nv_bfloat162*)&gu1);
            float2 gg = __bfloat1622float2(*(__nv_bfloat162*)&gu2);
            float2 ov = __bfloat1622float2(*(__nv_bfloat162*)&gu3);
            int eg = 64*(int)r + e;
            if (k < W0){
                cc0 = sigf(fv.x)*cc0 + sigf(iv.x)*tanh_fast(gg.x);
                hh0 = sigf(ov.x)*tanh_fast(cc0);
                g_Hwb[((size_t)(b0*TLEN + k))*RNNH + eg] = __float2bfloat16(hh0);
                g_Cw [((size_t)(b0*TLEN + k))*RNNH + eg] = cc0;
            }
            if (k < W1){
                cc1 = sigf(fv.y)*cc1 + sigf(iv.y)*tanh_fast(gg.y);
                hh1 = sigf(ov.y)*tanh_fast(cc1);
                g_Hwb[((size_t)(b1*TLEN + k))*RNNH + eg] = __float2bfloat16(hh1);
                g_Cw [((size_t)(b1*TLEN + k))*RNNH + eg] = cc1;
            }
        }
        // pack h pairs (e even with e+1 from lane+4) and broadcast
        float h0o = __shfl_xor_sync(0xffffffffu, hh0, 4);
        float h1o = __shfl_xor_sync(0xffffffffu, hh1, 4);
        if ((lam & 7) == 0){
            __nv_bfloat162 pk0 = __floats2bfloat162_rn(hh0, h0o);
            __nv_bfloat162 pk1 = __floats2bfloat162_rn(hh1, h1o);
            unsigned v0 = *(unsigned*)&pk0;
            unsigned v1 = *(unsigned*)&pk1;
            int widx = 32*(int)r + w*4 + (lam >> 3);   // pair index within batch
            unsigned woff0 = (unsigned)(CH_HB + p2*1024 +       widx*4);
            unsigned woff1 = (unsigned)(CH_HB + p2*1024 + 512 + widx*4);
            unsigned moff = (unsigned)(CH_MB + p2*8);
            #pragma unroll
            for (int qq = 0; qq < 4; qq++){
                asm volatile("st.async.shared::cluster.mbarrier::complete_tx::bytes.b32 "
                             "[%0], %1, [%2];"
                             :: "r"(peer[qq] + woff0), "r"(v0), "r"(peer[qq] + moff)
                             : "memory");
                asm volatile("st.async.shared::cluster.mbarrier::complete_tx::bytes.b32 "
                             "[%0], %1, [%2];"
                             :: "r"(peer[qq] + woff1), "r"(v1), "r"(peer[qq] + moff)
                             : "memory");
            }
        }
    }
    asm volatile("barrier.cluster.arrive.aligned;" ::: "memory");
    asm volatile("barrier.cluster.wait.aligned;"   ::: "memory");
}

// ---------------- L5: parallel per-step LSTM cell apply --------------------------
__global__ void k_apply(){
    int m = blockIdx.x;
    int d = threadIdx.x;          // 256
    int b = m >> 9;
    int j = g_cidx[m];
    size_t gbase = (size_t)m*GATES;
    float iv = __bfloat162float(g_G1b[gbase +       d]);
    float fv = __bfloat162float(g_G1b[gbase + 256 + d]);
    float gv = __bfloat162float(g_G1b[gbase + 512 + d]);
    float ov = __bfloat162float(g_G1b[gbase + 768 + d]);
    float cprev = 0.f;
    if (j >= 0){
        size_t hbase = (size_t)(b*TLEN + j)*GATES;
        iv += __bfloat162float(g_H2b[hbase +       d]);
        fv += __bfloat162float(g_H2b[hbase + 256 + d]);
        gv += __bfloat162float(g_H2b[hbase + 512 + d]);
        ov += __bfloat162float(g_H2b[hbase + 768 + d]);
        cprev = g_Cw[(size_t)(b*TLEN + j)*RNNH + d];
    }
    float cc = sigf(fv)*cprev + sigf(iv)*tanh_fast(gv);
    g_hsb[(size_t)m*RNNH + d] = __float2bfloat16(sigf(ov)*tanh_fast(cc));
}

// ---------------- L6: logits mma GEMM ([hs|enc] @ lw^T) + fused log_softmax ------
#define LG_SMEM (128*132*4)
__global__ void __launch_bounds__(256) k_logits(const int* __restrict__ lengths,
                                                float* __restrict__ out, int dup){
    __shared__ bf16 sA[128*SSTR];
    __shared__ bf16 sW[128*SSTR];
    float* sC = (float*)chsm;    // [128][132]
    int row0 = blockIdx.x * 128;
    int tid = threadIdx.x;
    int lane = tid & 31, wid = tid >> 5;
    int warp_m = wid & 3, warp_n = wid >> 2;
    int lrow = tid >> 2, lseg = tid & 3;

    unsigned sAb = (unsigned)__cvta_generic_to_shared(sA);
    unsigned sWb = (unsigned)__cvta_generic_to_shared(sW);
    unsigned aAddr = sAb + (unsigned)(((warp_m*32 + (lane&15))*SSTR + (lane>>4)*8)*2);
    unsigned bAddr = sWb + (unsigned)(((warp_n*64 + ((lane>>4)<<3) + (lane&7))*SSTR
                                      + ((lane>>3)&1)*8)*2);
    float acc[2][8][4];
    #pragma unroll
    for (int mi=0;mi<2;mi++)
        #pragma unroll
        for (int j=0;j<8;j++)
            #pragma unroll
            for (int q=0;q<4;q++) acc[mi][j][q] = 0.f;

    for (int k0 = 0; k0 < 768; k0 += 32){
        int kk = k0 + lseg*8;
        int m0 = row0 + lrow;
        uint4 a0, a1;
        if (kk < 256){
            a0 = *(const uint4*)&g_hsb[(size_t)m0*RNNH + kk];
            a1 = *(const uint4*)&g_hsb[(size_t)(m0+64)*RNNH + kk];
        } else {
            a0 = *(const uint4*)&g_encb[(size_t)m0*ENCD + kk - 256];
            a1 = *(const uint4*)&g_encb[(size_t)(m0+64)*ENCD + kk - 256];
        }
        uint4 w0 = *(const uint4*)&g_lwb[(size_t)lrow*768 + kk];
        uint4 w1 = *(const uint4*)&g_lwb[(size_t)(lrow+64)*768 + kk];
        *(uint4*)&sA[lrow*SSTR + lseg*8]      = a0;
        *(uint4*)&sA[(lrow+64)*SSTR + lseg*8] = a1;
        *(uint4*)&sW[lrow*SSTR + lseg*8]      = w0;
        *(uint4*)&sW[(lrow+64)*SSTR + lseg*8] = w1;
        __syncthreads();
        #pragma unroll
        for (int ks = 0; ks < 32; ks += 16){
            unsigned af[2][4], bfg[4][4];
            #pragma unroll
            for (int mi=0;mi<2;mi++)
                ldm_x4(aAddr + mi*16*SSTR*2 + ks*2, af[mi][0],af[mi][1],af[mi][2],af[mi][3]);
            #pragma unroll
            for (int p=0;p<4;p++)
                ldm_x4(bAddr + p*16*SSTR*2 + ks*2, bfg[p][0],bfg[p][1],bfg[p][2],bfg[p][3]);
            #pragma unroll
            for (int mi=0;mi<2;mi++)
                #pragma unroll
                for (int j=0;j<8;j++)
                    mma16816(acc[mi][j], af[mi], &bfg[j>>1][(j&1)*2]);
        }
        __syncthreads();
    }
    #pragma unroll
    for (int mi=0;mi<2;mi++)
        #pragma unroll
        for (int j=0;j<8;j++)
            #pragma unroll
            for (int q=0;q<2;q++){
                int rl = warp_m*32 + mi*16 + q*8 + (lane>>2);
                int cl = warp_n*64 + j*8 + (lane&3)*2;
                *(float2*)&sC[rl*132 + cl] = make_float2(acc[mi][j][q*2], acc[mi][j][q*2+1]);
            }
    __syncthreads();
    for (int rr = 0; rr < 16; rr++){
        int rl = wid*16 + rr;
        int m = row0 + rl;
        int b = m >> 9, t = m & 511;
        int L = lengths[b];
        float v[4];
        float vmax = -3.0e38f;
        #pragma unroll
        for (int u=0;u<4;u++){
            int n = lane + u*32;
            float x = sC[rl*132 + n];
            if (t == 0 && n == 0) x = -1e30f;
            if (t >= L) x = 0.f;
            v[u] = x;
            vmax = fmaxf(vmax, x);
        }
        #pragma unroll
        for (int d=16; d>=1; d>>=1) vmax = fmaxf(vmax, __shfl_xor_sync(0xffffffffu, vmax, d, 32));
        float ssum = 0.f;
        #pragma unroll
        for (int u=0;u<4;u++) ssum += expf(v[u] - vmax);
        #pragma unroll
        for (int d=16; d>=1; d>>=1) ssum += __shfl_xor_sync(0xffffffffu, ssum, d, 32);
        float lse = vmax + logf(ssum);
        #pragma unroll
        for (int u=0;u<4;u++){
            int n = lane + u*32;
            size_t idx = (size_t)m*LABEL + n;
            float res = v[u] - lse;
            out[idx] = res;
            if (dup) out[(size_t)OUTN + idx] = res;
        }
    }
}

// ---------------- launcher -------------------------------------------------------
extern "C" void kernel_launch(void* const* d_in, const int* in_sizes, int n_in,
                              void* d_out, int out_size){
    const float* enc  = (const float*)d_in[0];
    const int*   bnd  = (const int*)  d_in[1];
    const int*   pos  = (const int*)  d_in[2];
    const int*   len  = (const int*)  d_in[3];
    const float* w_ih = (const float*)d_in[4];
    const float* w_hh = (const float*)d_in[5];
    const float* b_ih = (const float*)d_in[6];
    const float* b_hh = (const float*)d_in[7];
    const float* ptab = (const float*)d_in[8];
    const float* lw   = (const float*)d_in[9];
    const float* cw   = (const float*)d_in[10];
    const float* cb   = (const float*)d_in[11];
    float* out = (float*)d_out;
    int dup = (out_size >= 2*OUTN) ? 1 : 0;

    void* p;
    cudaGetSymbolAddress(&p, g_Hwb);    bf16* Hwb  = (bf16*)p;
    cudaGetSymbolAddress(&p, g_H2b);    bf16* H2b  = (bf16*)p;
    cudaGetSymbolAddress(&p, g_whh_bf); bf16* whhb = (bf16*)p;

    cudaFuncSetAttribute(k_zg1,    cudaFuncAttributeMaxDynamicSharedMemorySize, ZG_SMEM);
    cudaFuncSetAttribute(k_chain,  cudaFuncAttributeMaxDynamicSharedMemorySize, CH_SMEM);
    cudaFuncSetAttribute(k_logits, cudaFuncAttributeMaxDynamicSharedMemorySize, LG_SMEM);

    // launch 0: conversions + boundary scan
    k_conv_scan<<<CONV_BLOCKS + 8, 256>>>(enc, cw, w_ih, w_hh, lw, bnd);
    // launch 1: zin build
    k_build_zin<<<dim3(2, BATCH), 512>>>(enc, bnd, pos, ptab);
    // launch 2: fused z + G1 GEMM
    k_zg1<<<MROWS/128, 256, ZG_SMEM>>>(cb, b_ih, b_hh);
    // launch 3 (ncu lands here): carry chain (in-warp gate gather)
    k_chain<<<(BATCH/2)*4, 256, CH_SMEM>>>();
    // launch 4: H2 = Hw @ w_hh^T (ragged skip)
    k_gemm_mma<2><<<dim3(GATES/128, MROWS/128), 256>>>(Hwb, whhb, H2b, RNNH, GATES,
                                                        nullptr, nullptr);
    // launch 5: parallel per-step LSTM outputs
    k_apply<<<MROWS, 256>>>();
    // launch 6: logits + masking + log_softmax
    k_logits<<<MROWS/128, 256, LG_SMEM>>>(len, out, dup);
}